// round 11
// baseline (speedup 1.0000x reference)
#include <cuda_runtime.h>
#include <cuda_fp16.h>
#include <cstdint>
#include <math.h>

#define OUT_ELEMS (16*256*2048)
#define KV_ELEMS  (16*32*512*64)

// Scratch (device globals)
__device__ __half g_xh[4096*2048];        // x in fp16
__device__ __half g_wh[4*2048*2048];      // Wq,Wk,Wv,Wo in fp16
__device__ __half g_qh[16*32*256*64];     // roped Q fp16 [B,H,T,64]
__device__ __half g_kh[16*32*512*64];     // attention K fp16 (past unroped + cur roped)
__device__ __half g_vh[16*32*512*64];     // attention V fp16
__device__ __half g_ah[4096*2048];        // attention out fp16, token-major
__device__ float  g_rope[256*32*2];       // (t,i) -> cos,sin

// ---------------------------------------------------------------------------
// helpers
// ---------------------------------------------------------------------------
__device__ __forceinline__ void mma16(float* d, const uint32_t* a, const uint32_t* b){
    asm volatile("mma.sync.aligned.m16n8k16.row.col.f32.f16.f16.f32 "
                 "{%0,%1,%2,%3},{%4,%5,%6,%7},{%8,%9},{%0,%1,%2,%3};"
                 : "+f"(d[0]),"+f"(d[1]),"+f"(d[2]),"+f"(d[3])
                 : "r"(a[0]),"r"(a[1]),"r"(a[2]),"r"(a[3]),"r"(b[0]),"r"(b[1]));
}
__device__ __forceinline__ void cpa16(uint32_t s, const void* g){
    asm volatile("cp.async.cg.shared.global [%0], [%1], 16;" :: "r"(s),"l"(g));
}
__device__ __forceinline__ void ldmx4(uint32_t* r, uint32_t addr){
    asm volatile("ldmatrix.sync.aligned.m8n8.x4.shared.b16 {%0,%1,%2,%3}, [%4];"
                 : "=r"(r[0]),"=r"(r[1]),"=r"(r[2]),"=r"(r[3]) : "r"(addr));
}
__device__ __forceinline__ void ldmx4t(uint32_t* r, uint32_t addr){
    asm volatile("ldmatrix.sync.aligned.m8n8.x4.trans.shared.b16 {%0,%1,%2,%3}, [%4];"
                 : "=r"(r[0]),"=r"(r[1]),"=r"(r[2]),"=r"(r[3]) : "r"(addr));
}
__device__ __forceinline__ uint32_t pkh2(float a, float b){
    __half2 h = __floats2half2_rn(a,b);
    return *(uint32_t*)&h;
}

// ---------------------------------------------------------------------------
// prep: x / Wq / Wk / Wv -> fp16, plus RoPE table (Wo handled in attn launch)
// ---------------------------------------------------------------------------
__global__ void prep_kernel(const float4* __restrict__ x,
                            const float4* __restrict__ wq, const float4* __restrict__ wk,
                            const float4* __restrict__ wv,
                            const int* __restrict__ pos){
    int seg = blockIdx.y;
    if(seg==0 && blockIdx.x < 32){
        int idx = blockIdx.x*blockDim.x + threadIdx.x;   // 8192 entries
        int t = idx >> 5, i = idx & 31;
        double invf = pow(10000.0, -2.0*(double)i/64.0);
        float ang = (float)(pos[0] + t) * (float)invf;
        g_rope[2*idx]   = (float)cos((double)ang);
        g_rope[2*idx+1] = (float)sin((double)ang);
    }
    const float4* src; __half* dst; int n;
    if(seg==0){ src = x; dst = g_xh; n = 2097152; }
    else{
        const float4* ws[3] = {wq,wk,wv};
        src = ws[seg-1]; dst = g_wh + (size_t)(seg-1)*4194304; n = 1048576;
    }
    for(int i = blockIdx.x*blockDim.x + threadIdx.x; i < n; i += gridDim.x*blockDim.x){
        float4 v = src[i];
        uint2 p;
        p.x = pkh2(v.x, v.y);
        p.y = pkh2(v.z, v.w);
        *(uint2*)&dst[(size_t)i*4] = p;
    }
}

// ---------------------------------------------------------------------------
// fp16 GEMM + fused past-KV copy on blockIdx.z==3 (MODE 0).
// BM=128, BN=128, BK=64, 128 threads, 4 warps (2m x 2n), warp tile 64x64.
// 2 CTAs/SM; explicit fragment double-buffer hides LDSM latency inside kt.
// ---------------------------------------------------------------------------
#define GW 36                              // words (u32) per smem row
#define GEMM_SMEM (2*2*128*GW*4)           // 73728 B

extern __shared__ float smf[];

template<int MODE>
__global__ void __launch_bounds__(128,2)
gemm_h(const float4* __restrict__ pk4, const float4* __restrict__ pv4,
       float* __restrict__ nk, float* __restrict__ nv, float* __restrict__ outp)
{
    int tid = threadIdx.x;

    if(MODE==0 && blockIdx.z==3){
        // past-KV copy CTAs (bandwidth-bound, overlap with compute CTAs)
        int bh = blockIdx.y*16 + blockIdx.x;    // 0..511
        float4* nk4 = (float4*)nk;
        float4* nv4 = (float4*)nv;
        #pragma unroll 4
        for(int it=0; it<32; it++){
            int off = it*128 + tid;
            float4 k = pk4[(size_t)bh*8192 + 4096 + off];
            float4 v = pv4[(size_t)bh*8192 + 4096 + off];
            nk4[(size_t)bh*8192 + off] = k;
            nv4[(size_t)bh*8192 + off] = v;
            uint2 kp, vp;
            kp.x = pkh2(k.x,k.y); kp.y = pkh2(k.z,k.w);
            vp.x = pkh2(v.x,v.y); vp.y = pkh2(v.z,v.w);
            *(uint2*)&g_kh[(size_t)bh*32768 + (size_t)off*4] = kp;
            *(uint2*)&g_vh[(size_t)bh*32768 + (size_t)off*4] = vp;
        }
        return;
    }

    uint32_t* Asw = (uint32_t*)smf;                 // [2][128][GW]
    uint32_t* Bsw = Asw + 2*128*GW;                 // [2][128][GW]

    int z = (MODE==0) ? blockIdx.z : 3;
    const __half* A = (MODE==0) ? g_xh : g_ah;
    const __half* W = g_wh + (size_t)z*4194304;
    int nblk = blockIdx.x, mblk = blockIdx.y;
    const __half* Ablk = A + (size_t)mblk*128*2048;
    const __half* Bblk = W + (size_t)nblk*128*2048;

    int lane = tid&31, wid = tid>>5;
    int wm = wid>>1, wn = wid&1, g = lane>>2, tig = lane&3;

    uint32_t sA = (uint32_t)__cvta_generic_to_shared(Asw);
    uint32_t sB = (uint32_t)__cvta_generic_to_shared(Bsw);

    const uint32_t STG = 128*GW*4;   // stage stride bytes

    uint32_t aAddr[4];
    #pragma unroll
    for(int mt=0;mt<4;mt++)
        aAddr[mt] = sA + (uint32_t)(((wm*64 + mt*16 + (lane&15))*GW + (lane>>4)*4)*4);
    uint32_t bAddr[4];
    #pragma unroll
    for(int j=0;j<4;j++)
        bAddr[j] = sB + (uint32_t)(((wn*64 + j*16 + (lane&7) + 8*(lane>>4))*GW + ((lane>>3)&1)*4)*4);

    float acc[4][8][4];
    #pragma unroll
    for(int a=0;a<4;a++)
      #pragma unroll
      for(int b=0;b<8;b++)
        #pragma unroll
        for(int c=0;c<4;c++) acc[a][b][c]=0.f;

    auto load_tile = [&](int kt, int s){
        #pragma unroll
        for(int p=0;p<8;p++){
            int i = p*128 + tid;
            int r = i>>3, c = i&7;
            cpa16(sA + (uint32_t)(s*STG) + (uint32_t)((r*GW + c*4)*4),
                  Ablk + (size_t)r*2048 + kt*64 + c*8);
        }
        #pragma unroll
        for(int p=0;p<8;p++){
            int i = p*128 + tid;
            int r = i>>3, c = i&7;
            cpa16(sB + (uint32_t)(s*STG) + (uint32_t)((r*GW + c*4)*4),
                  Bblk + (size_t)r*2048 + kt*64 + c*8);
        }
        asm volatile("cp.async.commit_group;");
    };

    auto load_frags = [&](uint32_t ko, uint32_t (*af)[4], uint32_t (*bf)[2]){
        #pragma unroll
        for(int mt=0;mt<4;mt++) ldmx4(af[mt], aAddr[mt] + ko);
        #pragma unroll
        for(int j=0;j<4;j++){
            uint32_t r[4];
            ldmx4(r, bAddr[j] + ko);
            bf[2*j][0]=r[0];   bf[2*j][1]=r[1];
            bf[2*j+1][0]=r[2]; bf[2*j+1][1]=r[3];
        }
    };

    load_tile(0,0);
    for(int kt=0; kt<32; kt++){
        if(kt+1 < 32){
            load_tile(kt+1, (kt+1)&1);
            asm volatile("cp.async.wait_group 1;");
        } else {
            asm volatile("cp.async.wait_group 0;");
        }
        __syncthreads();
        uint32_t so = (uint32_t)((kt&1)*STG);

        uint32_t af[2][4][4], bf[2][8][2];
        load_frags(so, af[0], bf[0]);
        #pragma unroll
        for(int kb=0; kb<4; kb++){
            int cur = kb&1, nxt = cur^1;
            if(kb < 3) load_frags(so + (kb+1)*32, af[nxt], bf[nxt]);
            #pragma unroll
            for(int mt=0;mt<4;mt++)
                #pragma unroll
                for(int nt=0;nt<8;nt++)
                    mma16(acc[mt][nt], af[cur][mt], bf[cur][nt]);
        }
        __syncthreads();
    }

    #pragma unroll
    for(int mt=0;mt<4;mt++){
        #pragma unroll
        for(int nt=0;nt<8;nt++){
            int row = mblk*128 + wm*64 + mt*16 + g;
            int col = nblk*128 + wn*64 + nt*8 + 2*tig;
            float c0=acc[mt][nt][0], c1=acc[mt][nt][1];
            float c2=acc[mt][nt][2], c3=acc[mt][nt][3];
            if(MODE==1){
                *(float2*)(outp + (size_t)row*2048 + col)     = make_float2(c0,c1);
                *(float2*)(outp + (size_t)(row+8)*2048 + col) = make_float2(c2,c3);
            } else {
                int t = row & 255, b = row >> 8;
                int h = col >> 6, d = col & 63, ii = d >> 1;
                if(z==2){
                    *(float2*)(nv + ((size_t)(b*32+h)*512 + 256 + t)*64 + d)     = make_float2(c0,c1);
                    *(float2*)(nv + ((size_t)(b*32+h)*512 + 256 + t + 8)*64 + d) = make_float2(c2,c3);
                    *(uint32_t*)&g_vh[((size_t)(b*32+h)*512 + 256 + t)*64 + d]     = pkh2(c0,c1);
                    *(uint32_t*)&g_vh[((size_t)(b*32+h)*512 + 256 + t + 8)*64 + d] = pkh2(c2,c3);
                } else {
                    float cs0 = g_rope[(t*32+ii)*2],     sn0 = g_rope[(t*32+ii)*2+1];
                    float cs1 = g_rope[((t+8)*32+ii)*2], sn1 = g_rope[((t+8)*32+ii)*2+1];
                    float r0 = c0*cs0 - c1*sn0, r1 = c0*sn0 + c1*cs0;
                    float r2 = c2*cs1 - c3*sn1, r3 = c2*sn1 + c3*cs1;
                    if(z==0){
                        *(uint32_t*)&g_qh[((size_t)(b*32+h)*256 + t)*64 + d]     = pkh2(r0,r1);
                        *(uint32_t*)&g_qh[((size_t)(b*32+h)*256 + t + 8)*64 + d] = pkh2(r2,r3);
                    } else {
                        *(float2*)(nk + ((size_t)(b*32+h)*512 + 256 + t)*64 + d)     = make_float2(c0,c1);
                        *(float2*)(nk + ((size_t)(b*32+h)*512 + 256 + t + 8)*64 + d) = make_float2(c2,c3);
                        *(uint32_t*)&g_kh[((size_t)(b*32+h)*512 + 256 + t)*64 + d]     = pkh2(r0,r1);
                        *(uint32_t*)&g_kh[((size_t)(b*32+h)*512 + 256 + t + 8)*64 + d] = pkh2(r2,r3);
                    }
                }
            }
        }
    }
}

// ---------------------------------------------------------------------------
// fp16 flash attention v3 (split-Q) + fused Wo->fp16 conversion CTAs.
// CTAs [0,1024): attention, one per (b,h,qhalf). CTAs [1024,1088): Wo convert.
// ---------------------------------------------------------------------------
#define QW 36                          // u32 words per staged Q row
#define KW 36                          // u32 words per K/V row (72 halves)
#define KV_STG (64*KW*4)               // 9216 B per K (or V) tile
#define ATTN_SMEM (4*KV_STG)           // 36864 B

__global__ void __launch_bounds__(256,2)
attn_kernel(const float4* __restrict__ wo)
{
    if(blockIdx.x >= 1024){
        int cid = blockIdx.x - 1024;               // 0..63
        __half* dst = g_wh + (size_t)3*4194304;
        for(int i = cid*256 + threadIdx.x; i < 1048576; i += 64*256){
            float4 v = wo[i];
            uint2 p;
            p.x = pkh2(v.x, v.y);
            p.y = pkh2(v.z, v.w);
            *(uint2*)&dst[(size_t)i*4] = p;
        }
        return;
    }

    uint32_t* S = (uint32_t*)smf;
    uint32_t sbase = (uint32_t)__cvta_generic_to_shared(S);

    int bh = blockIdx.x >> 1;
    int qbase = (blockIdx.x & 1) * 128;
    int tid = threadIdx.x, wid = tid>>5, lane = tid&31, g = lane>>2, tig = lane&3;

    // ---- phase 1: stage Q (128 rows), extract per-warp Q fragments ----
    {
        const uint4* q4 = (const uint4*)(g_qh + (size_t)bh*16384 + (size_t)qbase*64);
        int r = tid>>1, cb = (tid&1)*4;
        #pragma unroll
        for(int c=0;c<4;c++)
            *(uint4*)&S[r*QW + (cb+c)*4] = q4[(size_t)r*8 + cb + c];
    }
    __syncthreads();
    uint32_t qf[4][4];
    {
        uint32_t qa = sbase + (uint32_t)(((wid*16 + (lane&15))*QW + (lane>>4)*4)*4);
        #pragma unroll
        for(int kb=0;kb<4;kb++)
            ldmx4(qf[kb], qa + (uint32_t)(kb*32));
    }
    __syncthreads();   // Q reads done before cp.async overwrites S

    // ---- phase 2: K/V mainloop ----
    const __half* kg = g_kh + (size_t)bh*32768;
    const __half* vg = g_vh + (size_t)bh*32768;

    uint32_t kAddr[4];
    #pragma unroll
    for(int j=0;j<4;j++)
        kAddr[j] = sbase + (uint32_t)(((j*16 + (lane&7) + 8*(lane>>4))*KW + ((lane>>3)&1)*4)*4);

    auto load_kv = [&](int kt, int s){
        int r = tid>>2, cq = tid&3;
        uint32_t so = (uint32_t)(s*2*KV_STG);
        #pragma unroll
        for(int j=0;j<2;j++){
            int c = cq + j*4;
            cpa16(sbase + so + (uint32_t)((r*KW + c*4)*4),
                  kg + (size_t)(kt*64+r)*64 + c*8);
            cpa16(sbase + so + KV_STG + (uint32_t)((r*KW + c*4)*4),
                  vg + (size_t)(kt*64+r)*64 + c*8);
        }
        asm volatile("cp.async.commit_group;");
    };

    float o[8][4];
    #pragma unroll
    for(int b=0;b<8;b++)
        #pragma unroll
        for(int c=0;c<4;c++) o[b][c]=0.f;
    float lsum0 = 0.f, lsum1 = 0.f;

    const float SC = 0.125f * 1.44269504088896341f;
    int tw = qbase + wid*16;                 // warp's first q row (global t)
    int klim = tw + 15 + 256;                // max visible key for this warp

    load_kv(0,0);
    for(int kt=0;kt<8;kt++){
        asm volatile("cp.async.wait_group 0;");
        __syncthreads();
        if(kt+1 < 8) load_kv(kt+1, (kt+1)&1);
        if(kt*64 <= klim){
            uint32_t so = (uint32_t)((kt&1)*2*KV_STG);

            // --- S = Q K^T ---
            float s[8][4];
            #pragma unroll
            for(int b=0;b<8;b++)
                #pragma unroll
                for(int c=0;c<4;c++) s[b][c]=0.f;
            #pragma unroll
            for(int kb=0;kb<4;kb++){
                uint32_t bf[8][2];
                #pragma unroll
                for(int j=0;j<4;j++){
                    uint32_t r[4];
                    ldmx4(r, kAddr[j] + so + kb*32);
                    bf[2*j][0]=r[0];   bf[2*j][1]=r[1];
                    bf[2*j+1][0]=r[2]; bf[2*j+1][1]=r[3];
                }
                #pragma unroll
                for(int nt=0;nt<8;nt++)
                    mma16(s[nt], qf[kb], bf[nt]);
            }

            // --- softmax (no max subtraction) + pack P to A-frags ---
            uint32_t pf[4][4];
            bool needmask = (kt*64 + 63 > tw + 256);
            int t0 = tw + g;
            #pragma unroll
            for(int nt=0;nt<8;nt++){
                float p0 = exp2f(s[nt][0]*SC);
                float p1 = exp2f(s[nt][1]*SC);
                float p2 = exp2f(s[nt][2]*SC);
                float p3 = exp2f(s[nt][3]*SC);
                if(needmask){
                    int j0 = kt*64 + nt*8 + 2*tig;
                    if(j0   > t0+256) p0 = 0.f;
                    if(j0+1 > t0+256) p1 = 0.f;
                    if(j0   > t0+264) p2 = 0.f;
                    if(j0+1 > t0+264) p3 = 0.f;
                }
                lsum0 += p0 + p1;
                lsum1 += p2 + p3;
                s[nt][0]=p0; s[nt][1]=p1; s[nt][2]=p2; s[nt][3]=p3;
            }
            #pragma unroll
            for(int kb=0;kb<4;kb++){
                pf[kb][0] = pkh2(s[2*kb][0],   s[2*kb][1]);
                pf[kb][1] = pkh2(s[2*kb][2],   s[2*kb][3]);
                pf[kb][2] = pkh2(s[2*kb+1][0], s[2*kb+1][1]);
                pf[kb][3] = pkh2(s[2*kb+1][2], s[2*kb+1][3]);
            }

            // --- O += P V ---
            uint32_t vbase = sbase + so + KV_STG;
            #pragma unroll
            for(int kb=0;kb<4;kb++){
                uint32_t bf[8][2];
                #pragma unroll
                for(int np=0;np<4;np++){
                    int row = kb*16 + (lane&7) + 8*((lane>>3)&1);
                    int col = np*16 + 8*(lane>>4);
                    uint32_t r[4];
                    ldmx4t(r, vbase + (uint32_t)((row*KW*2 + col)*2));
                    bf[2*np][0]=r[0];   bf[2*np][1]=r[1];
                    bf[2*np+1][0]=r[2]; bf[2*np+1][1]=r[3];
                }
                #pragma unroll
                for(int nt=0;nt<8;nt++)
                    mma16(o[nt], pf[kb], bf[nt]);
            }
        }
    }

    // ---- reduce l across the quad, normalize, write ----
    int b = bh>>5, h = bh&31;
    lsum0 += __shfl_xor_sync(0xffffffffu, lsum0, 1);
    lsum0 += __shfl_xor_sync(0xffffffffu, lsum0, 2);
    lsum1 += __shfl_xor_sync(0xffffffffu, lsum1, 1);
    lsum1 += __shfl_xor_sync(0xffffffffu, lsum1, 2);
    float i0 = 1.f/lsum0, i1 = 1.f/lsum1;
    int t0 = qbase + wid*16 + g;
    #pragma unroll
    for(int nt=0;nt<8;nt++){
        int col = h*64 + nt*8 + 2*tig;
        *(uint32_t*)&g_ah[(size_t)(b*256+t0)*2048 + col]   = pkh2(o[nt][0]*i0, o[nt][1]*i0);
        *(uint32_t*)&g_ah[(size_t)(b*256+t0+8)*2048 + col] = pkh2(o[nt][2]*i1, o[nt][3]*i1);
    }
}

// ---------------------------------------------------------------------------
extern "C" void kernel_launch(void* const* d_in, const int* in_sizes, int n_in,
                              void* d_out, int out_size)
{
    (void)in_sizes; (void)n_in; (void)out_size;
    const float* x  = (const float*)d_in[0];
    const float* pk = (const float*)d_in[1];
    const float* pv = (const float*)d_in[2];
    const float* Wq = (const float*)d_in[3];
    const float* Wk = (const float*)d_in[4];
    const float* Wv = (const float*)d_in[5];
    const float* Wo = (const float*)d_in[6];
    const int*  pos = (const int*)d_in[7];

    float* out = (float*)d_out;
    float* nk  = out + OUT_ELEMS;
    float* nv  = nk + KV_ELEMS;

    cudaFuncSetAttribute(gemm_h<0>, cudaFuncAttributeMaxDynamicSharedMemorySize, GEMM_SMEM);
    cudaFuncSetAttribute(gemm_h<1>, cudaFuncAttributeMaxDynamicSharedMemorySize, GEMM_SMEM);
    cudaFuncSetAttribute(attn_kernel, cudaFuncAttributeMaxDynamicSharedMemorySize, ATTN_SMEM);

    prep_kernel<<<dim3(1024,4),256>>>((const float4*)x,(const float4*)Wq,(const float4*)Wk,
                                      (const float4*)Wv,pos);
    gemm_h<0><<<dim3(16,32,4),128,GEMM_SMEM>>>((const float4*)pk,(const float4*)pv,nk,nv,nullptr);
    attn_kernel<<<1088,256,ATTN_SMEM>>>((const float4*)Wo);
    gemm_h<1><<<dim3(16,32,1),128,GEMM_SMEM>>>(nullptr,nullptr,nullptr,nullptr,out);
}

// round 12
// speedup vs baseline: 1.1041x; 1.1041x over previous
#include <cuda_runtime.h>
#include <cuda_fp16.h>
#include <cstdint>
#include <math.h>

#define OUT_ELEMS (16*256*2048)
#define KV_ELEMS  (16*32*512*64)

// Scratch (device globals)
__device__ __half g_xh[4096*2048];        // x in fp16
__device__ __half g_wh[4*2048*2048];      // Wq,Wk,Wv,Wo in fp16
__device__ __half g_qh[16*32*256*64];     // roped Q fp16 [B,H,T,64]
__device__ __half g_kh[16*32*512*64];     // attention K fp16 (past unroped + cur roped)
__device__ __half g_vh[16*32*512*64];     // attention V fp16
__device__ __half g_ah[4096*2048];        // attention out fp16, token-major
__device__ float  g_rope[256*32*2];       // (t,i) -> cos,sin

// ---------------------------------------------------------------------------
// helpers
// ---------------------------------------------------------------------------
__device__ __forceinline__ void mma16(float* d, const uint32_t* a, const uint32_t* b){
    asm volatile("mma.sync.aligned.m16n8k16.row.col.f32.f16.f16.f32 "
                 "{%0,%1,%2,%3},{%4,%5,%6,%7},{%8,%9},{%0,%1,%2,%3};"
                 : "+f"(d[0]),"+f"(d[1]),"+f"(d[2]),"+f"(d[3])
                 : "r"(a[0]),"r"(a[1]),"r"(a[2]),"r"(a[3]),"r"(b[0]),"r"(b[1]));
}
__device__ __forceinline__ void cpa16(uint32_t s, const void* g){
    asm volatile("cp.async.cg.shared.global [%0], [%1], 16;" :: "r"(s),"l"(g));
}
__device__ __forceinline__ void ldmx4(uint32_t* r, uint32_t addr){
    asm volatile("ldmatrix.sync.aligned.m8n8.x4.shared.b16 {%0,%1,%2,%3}, [%4];"
                 : "=r"(r[0]),"=r"(r[1]),"=r"(r[2]),"=r"(r[3]) : "r"(addr));
}
__device__ __forceinline__ void ldmx4t(uint32_t* r, uint32_t addr){
    asm volatile("ldmatrix.sync.aligned.m8n8.x4.trans.shared.b16 {%0,%1,%2,%3}, [%4];"
                 : "=r"(r[0]),"=r"(r[1]),"=r"(r[2]),"=r"(r[3]) : "r"(addr));
}
__device__ __forceinline__ uint32_t pkh2(float a, float b){
    __half2 h = __floats2half2_rn(a,b);
    return *(uint32_t*)&h;
}

// ---------------------------------------------------------------------------
// prep: x / Wq / Wk / Wv -> fp16, plus RoPE table (Wo handled in attn launch)
// ---------------------------------------------------------------------------
__global__ void prep_kernel(const float4* __restrict__ x,
                            const float4* __restrict__ wq, const float4* __restrict__ wk,
                            const float4* __restrict__ wv,
                            const int* __restrict__ pos){
    int seg = blockIdx.y;
    if(seg==0 && blockIdx.x < 32){
        int idx = blockIdx.x*blockDim.x + threadIdx.x;   // 8192 entries
        int t = idx >> 5, i = idx & 31;
        double invf = pow(10000.0, -2.0*(double)i/64.0);
        float ang = (float)(pos[0] + t) * (float)invf;
        g_rope[2*idx]   = (float)cos((double)ang);
        g_rope[2*idx+1] = (float)sin((double)ang);
    }
    const float4* src; __half* dst; int n;
    if(seg==0){ src = x; dst = g_xh; n = 2097152; }
    else{
        const float4* ws[3] = {wq,wk,wv};
        src = ws[seg-1]; dst = g_wh + (size_t)(seg-1)*4194304; n = 1048576;
    }
    for(int i = blockIdx.x*blockDim.x + threadIdx.x; i < n; i += gridDim.x*blockDim.x){
        float4 v = src[i];
        uint2 p;
        p.x = pkh2(v.x, v.y);
        p.y = pkh2(v.z, v.w);
        *(uint2*)&dst[(size_t)i*4] = p;
    }
}

// ---------------------------------------------------------------------------
// fp16 GEMM (round-8 config — converged) + fused past-KV copy on z==3 (MODE 0)
// BM=128, BN=128, BK=64, 128 threads, 4 warps (2m x 2n), warp tile 64x64,
// double-buffered cp.async, 3 CTAs/SM.
// ---------------------------------------------------------------------------
#define GW 36                              // words (u32) per smem row
#define GEMM_SMEM (2*2*128*GW*4)           // 73728 B

extern __shared__ float smf[];

template<int MODE>
__global__ void __launch_bounds__(128,3)
gemm_h(const float4* __restrict__ pk4, const float4* __restrict__ pv4,
       float* __restrict__ nk, float* __restrict__ nv, float* __restrict__ outp)
{
    int tid = threadIdx.x;

    if(MODE==0 && blockIdx.z==3){
        // past-KV copy CTAs (bandwidth-bound, overlap with compute CTAs)
        int bh = blockIdx.y*16 + blockIdx.x;    // 0..511
        float4* nk4 = (float4*)nk;
        float4* nv4 = (float4*)nv;
        #pragma unroll 4
        for(int it=0; it<32; it++){
            int off = it*128 + tid;
            float4 k = pk4[(size_t)bh*8192 + 4096 + off];
            float4 v = pv4[(size_t)bh*8192 + 4096 + off];
            nk4[(size_t)bh*8192 + off] = k;
            nv4[(size_t)bh*8192 + off] = v;
            uint2 kp, vp;
            kp.x = pkh2(k.x,k.y); kp.y = pkh2(k.z,k.w);
            vp.x = pkh2(v.x,v.y); vp.y = pkh2(v.z,v.w);
            *(uint2*)&g_kh[(size_t)bh*32768 + (size_t)off*4] = kp;
            *(uint2*)&g_vh[(size_t)bh*32768 + (size_t)off*4] = vp;
        }
        return;
    }

    uint32_t* Asw = (uint32_t*)smf;                 // [2][128][GW]
    uint32_t* Bsw = Asw + 2*128*GW;                 // [2][128][GW]

    int z = (MODE==0) ? blockIdx.z : 3;
    const __half* A = (MODE==0) ? g_xh : g_ah;
    const __half* W = g_wh + (size_t)z*4194304;
    int nblk = blockIdx.x, mblk = blockIdx.y;
    const __half* Ablk = A + (size_t)mblk*128*2048;
    const __half* Bblk = W + (size_t)nblk*128*2048;

    int lane = tid&31, wid = tid>>5;
    int wm = wid>>1, wn = wid&1, g = lane>>2, tig = lane&3;

    uint32_t sA = (uint32_t)__cvta_generic_to_shared(Asw);
    uint32_t sB = (uint32_t)__cvta_generic_to_shared(Bsw);

    const uint32_t STG = 128*GW*4;   // stage stride bytes

    uint32_t aAddr[4];
    #pragma unroll
    for(int mt=0;mt<4;mt++)
        aAddr[mt] = sA + (uint32_t)(((wm*64 + mt*16 + (lane&15))*GW + (lane>>4)*4)*4);
    uint32_t bAddr[4];
    #pragma unroll
    for(int j=0;j<4;j++)
        bAddr[j] = sB + (uint32_t)(((wn*64 + j*16 + (lane&7) + 8*(lane>>4))*GW + ((lane>>3)&1)*4)*4);

    float acc[4][8][4];
    #pragma unroll
    for(int a=0;a<4;a++)
      #pragma unroll
      for(int b=0;b<8;b++)
        #pragma unroll
        for(int c=0;c<4;c++) acc[a][b][c]=0.f;

    auto load_tile = [&](int kt, int s){
        #pragma unroll
        for(int p=0;p<8;p++){
            int i = p*128 + tid;
            int r = i>>3, c = i&7;
            cpa16(sA + (uint32_t)(s*STG) + (uint32_t)((r*GW + c*4)*4),
                  Ablk + (size_t)r*2048 + kt*64 + c*8);
        }
        #pragma unroll
        for(int p=0;p<8;p++){
            int i = p*128 + tid;
            int r = i>>3, c = i&7;
            cpa16(sB + (uint32_t)(s*STG) + (uint32_t)((r*GW + c*4)*4),
                  Bblk + (size_t)r*2048 + kt*64 + c*8);
        }
        asm volatile("cp.async.commit_group;");
    };

    load_tile(0,0);
    for(int kt=0; kt<32; kt++){
        if(kt+1 < 32){
            load_tile(kt+1, (kt+1)&1);
            asm volatile("cp.async.wait_group 1;");
        } else {
            asm volatile("cp.async.wait_group 0;");
        }
        __syncthreads();
        uint32_t so = (uint32_t)((kt&1)*STG);
        #pragma unroll
        for(int kb=0; kb<4; kb++){
            uint32_t ko = so + kb*32;
            uint32_t af[4][4];
            #pragma unroll
            for(int mt=0;mt<4;mt++) ldmx4(af[mt], aAddr[mt] + ko);
            uint32_t bf[8][2];
            #pragma unroll
            for(int j=0;j<4;j++){
                uint32_t r[4];
                ldmx4(r, bAddr[j] + ko);
                bf[2*j][0]=r[0];   bf[2*j][1]=r[1];
                bf[2*j+1][0]=r[2]; bf[2*j+1][1]=r[3];
            }
            #pragma unroll
            for(int mt=0;mt<4;mt++)
                #pragma unroll
                for(int nt=0;nt<8;nt++)
                    mma16(acc[mt][nt], af[mt], bf[nt]);
        }
        __syncthreads();
    }

    #pragma unroll
    for(int mt=0;mt<4;mt++){
        #pragma unroll
        for(int nt=0;nt<8;nt++){
            int row = mblk*128 + wm*64 + mt*16 + g;
            int col = nblk*128 + wn*64 + nt*8 + 2*tig;
            float c0=acc[mt][nt][0], c1=acc[mt][nt][1];
            float c2=acc[mt][nt][2], c3=acc[mt][nt][3];
            if(MODE==1){
                *(float2*)(outp + (size_t)row*2048 + col)     = make_float2(c0,c1);
                *(float2*)(outp + (size_t)(row+8)*2048 + col) = make_float2(c2,c3);
            } else {
                int t = row & 255, b = row >> 8;
                int h = col >> 6, d = col & 63, ii = d >> 1;
                if(z==2){
                    *(float2*)(nv + ((size_t)(b*32+h)*512 + 256 + t)*64 + d)     = make_float2(c0,c1);
                    *(float2*)(nv + ((size_t)(b*32+h)*512 + 256 + t + 8)*64 + d) = make_float2(c2,c3);
                    *(uint32_t*)&g_vh[((size_t)(b*32+h)*512 + 256 + t)*64 + d]     = pkh2(c0,c1);
                    *(uint32_t*)&g_vh[((size_t)(b*32+h)*512 + 256 + t + 8)*64 + d] = pkh2(c2,c3);
                } else {
                    float cs0 = g_rope[(t*32+ii)*2],     sn0 = g_rope[(t*32+ii)*2+1];
                    float cs1 = g_rope[((t+8)*32+ii)*2], sn1 = g_rope[((t+8)*32+ii)*2+1];
                    float r0 = c0*cs0 - c1*sn0, r1 = c0*sn0 + c1*cs0;
                    float r2 = c2*cs1 - c3*sn1, r3 = c2*sn1 + c3*cs1;
                    if(z==0){
                        *(uint32_t*)&g_qh[((size_t)(b*32+h)*256 + t)*64 + d]     = pkh2(r0,r1);
                        *(uint32_t*)&g_qh[((size_t)(b*32+h)*256 + t + 8)*64 + d] = pkh2(r2,r3);
                    } else {
                        *(float2*)(nk + ((size_t)(b*32+h)*512 + 256 + t)*64 + d)     = make_float2(c0,c1);
                        *(float2*)(nk + ((size_t)(b*32+h)*512 + 256 + t + 8)*64 + d) = make_float2(c2,c3);
                        *(uint32_t*)&g_kh[((size_t)(b*32+h)*512 + 256 + t)*64 + d]     = pkh2(r0,r1);
                        *(uint32_t*)&g_kh[((size_t)(b*32+h)*512 + 256 + t + 8)*64 + d] = pkh2(r2,r3);
                    }
                }
            }
        }
    }
}

// ---------------------------------------------------------------------------
// fp16 flash attention v3 (split-Q) + fused Wo->fp16 conversion CTAs.
// CTAs [0,1024): attention, one per (b,h,qhalf). CTAs [1024,1088): Wo convert.
// ---------------------------------------------------------------------------
#define QW 36                          // u32 words per staged Q row
#define KW 36                          // u32 words per K/V row (72 halves)
#define KV_STG (64*KW*4)               // 9216 B per K (or V) tile
#define ATTN_SMEM (4*KV_STG)           // 36864 B

__global__ void __launch_bounds__(256,2)
attn_kernel(const float4* __restrict__ wo)
{
    if(blockIdx.x >= 1024){
        int cid = blockIdx.x - 1024;               // 0..63
        __half* dst = g_wh + (size_t)3*4194304;
        for(int i = cid*256 + threadIdx.x; i < 1048576; i += 64*256){
            float4 v = wo[i];
            uint2 p;
            p.x = pkh2(v.x, v.y);
            p.y = pkh2(v.z, v.w);
            *(uint2*)&dst[(size_t)i*4] = p;
        }
        return;
    }

    uint32_t* S = (uint32_t*)smf;
    uint32_t sbase = (uint32_t)__cvta_generic_to_shared(S);

    int bh = blockIdx.x >> 1;
    int qbase = (blockIdx.x & 1) * 128;
    int tid = threadIdx.x, wid = tid>>5, lane = tid&31, g = lane>>2, tig = lane&3;

    // ---- phase 1: stage Q (128 rows), extract per-warp Q fragments ----
    {
        const uint4* q4 = (const uint4*)(g_qh + (size_t)bh*16384 + (size_t)qbase*64);
        int r = tid>>1, cb = (tid&1)*4;
        #pragma unroll
        for(int c=0;c<4;c++)
            *(uint4*)&S[r*QW + (cb+c)*4] = q4[(size_t)r*8 + cb + c];
    }
    __syncthreads();
    uint32_t qf[4][4];
    {
        uint32_t qa = sbase + (uint32_t)(((wid*16 + (lane&15))*QW + (lane>>4)*4)*4);
        #pragma unroll
        for(int kb=0;kb<4;kb++)
            ldmx4(qf[kb], qa + (uint32_t)(kb*32));
    }
    __syncthreads();   // Q reads done before cp.async overwrites S

    // ---- phase 2: K/V mainloop ----
    const __half* kg = g_kh + (size_t)bh*32768;
    const __half* vg = g_vh + (size_t)bh*32768;

    uint32_t kAddr[4];
    #pragma unroll
    for(int j=0;j<4;j++)
        kAddr[j] = sbase + (uint32_t)(((j*16 + (lane&7) + 8*(lane>>4))*KW + ((lane>>3)&1)*4)*4);

    auto load_kv = [&](int kt, int s){
        int r = tid>>2, cq = tid&3;
        uint32_t so = (uint32_t)(s*2*KV_STG);
        #pragma unroll
        for(int j=0;j<2;j++){
            int c = cq + j*4;
            cpa16(sbase + so + (uint32_t)((r*KW + c*4)*4),
                  kg + (size_t)(kt*64+r)*64 + c*8);
            cpa16(sbase + so + KV_STG + (uint32_t)((r*KW + c*4)*4),
                  vg + (size_t)(kt*64+r)*64 + c*8);
        }
        asm volatile("cp.async.commit_group;");
    };

    float o[8][4];
    #pragma unroll
    for(int b=0;b<8;b++)
        #pragma unroll
        for(int c=0;c<4;c++) o[b][c]=0.f;
    float lsum0 = 0.f, lsum1 = 0.f;

    const float SC = 0.125f * 1.44269504088896341f;
    int tw = qbase + wid*16;                 // warp's first q row (global t)
    int klim = tw + 15 + 256;                // max visible key for this warp

    load_kv(0,0);
    for(int kt=0;kt<8;kt++){
        asm volatile("cp.async.wait_group 0;");
        __syncthreads();
        if(kt+1 < 8) load_kv(kt+1, (kt+1)&1);
        if(kt*64 <= klim){
            uint32_t so = (uint32_t)((kt&1)*2*KV_STG);

            // --- S = Q K^T ---
            float s[8][4];
            #pragma unroll
            for(int b=0;b<8;b++)
                #pragma unroll
                for(int c=0;c<4;c++) s[b][c]=0.f;
            #pragma unroll
            for(int kb=0;kb<4;kb++){
                uint32_t bf[8][2];
                #pragma unroll
                for(int j=0;j<4;j++){
                    uint32_t r[4];
                    ldmx4(r, kAddr[j] + so + kb*32);
                    bf[2*j][0]=r[0];   bf[2*j][1]=r[1];
                    bf[2*j+1][0]=r[2]; bf[2*j+1][1]=r[3];
                }
                #pragma unroll
                for(int nt=0;nt<8;nt++)
                    mma16(s[nt], qf[kb], bf[nt]);
            }

            // --- softmax (no max subtraction) + pack P to A-frags ---
            uint32_t pf[4][4];
            bool needmask = (kt*64 + 63 > tw + 256);
            int t0 = tw + g;
            #pragma unroll
            for(int nt=0;nt<8;nt++){
                float p0 = exp2f(s[nt][0]*SC);
                float p1 = exp2f(s[nt][1]*SC);
                float p2 = exp2f(s[nt][2]*SC);
                float p3 = exp2f(s[nt][3]*SC);
                if(needmask){
                    int j0 = kt*64 + nt*8 + 2*tig;
                    if(j0   > t0+256) p0 = 0.f;
                    if(j0+1 > t0+256) p1 = 0.f;
                    if(j0   > t0+264) p2 = 0.f;
                    if(j0+1 > t0+264) p3 = 0.f;
                }
                lsum0 += p0 + p1;
                lsum1 += p2 + p3;
                s[nt][0]=p0; s[nt][1]=p1; s[nt][2]=p2; s[nt][3]=p3;
            }
            #pragma unroll
            for(int kb=0;kb<4;kb++){
                pf[kb][0] = pkh2(s[2*kb][0],   s[2*kb][1]);
                pf[kb][1] = pkh2(s[2*kb][2],   s[2*kb][3]);
                pf[kb][2] = pkh2(s[2*kb+1][0], s[2*kb+1][1]);
                pf[kb][3] = pkh2(s[2*kb+1][2], s[2*kb+1][3]);
            }

            // --- O += P V ---
            uint32_t vbase = sbase + so + KV_STG;
            #pragma unroll
            for(int kb=0;kb<4;kb++){
                uint32_t bf[8][2];
                #pragma unroll
                for(int np=0;np<4;np++){
                    int row = kb*16 + (lane&7) + 8*((lane>>3)&1);
                    int col = np*16 + 8*(lane>>4);
                    uint32_t r[4];
                    ldmx4t(r, vbase + (uint32_t)((row*KW*2 + col)*2));
                    bf[2*np][0]=r[0];   bf[2*np][1]=r[1];
                    bf[2*np+1][0]=r[2]; bf[2*np+1][1]=r[3];
                }
                #pragma unroll
                for(int nt=0;nt<8;nt++)
                    mma16(o[nt], pf[kb], bf[nt]);
            }
        }
    }

    // ---- reduce l across the quad, normalize, write ----
    int b = bh>>5, h = bh&31;
    lsum0 += __shfl_xor_sync(0xffffffffu, lsum0, 1);
    lsum0 += __shfl_xor_sync(0xffffffffu, lsum0, 2);
    lsum1 += __shfl_xor_sync(0xffffffffu, lsum1, 1);
    lsum1 += __shfl_xor_sync(0xffffffffu, lsum1, 2);
    float i0 = 1.f/lsum0, i1 = 1.f/lsum1;
    int t0 = qbase + wid*16 + g;
    #pragma unroll
    for(int nt=0;nt<8;nt++){
        int col = h*64 + nt*8 + 2*tig;
        *(uint32_t*)&g_ah[(size_t)(b*256+t0)*2048 + col]   = pkh2(o[nt][0]*i0, o[nt][1]*i0);
        *(uint32_t*)&g_ah[(size_t)(b*256+t0+8)*2048 + col] = pkh2(o[nt][2]*i1, o[nt][3]*i1);
    }
}

// ---------------------------------------------------------------------------
extern "C" void kernel_launch(void* const* d_in, const int* in_sizes, int n_in,
                              void* d_out, int out_size)
{
    (void)in_sizes; (void)n_in; (void)out_size;
    const float* x  = (const float*)d_in[0];
    const float* pk = (const float*)d_in[1];
    const float* pv = (const float*)d_in[2];
    const float* Wq = (const float*)d_in[3];
    const float* Wk = (const float*)d_in[4];
    const float* Wv = (const float*)d_in[5];
    const float* Wo = (const float*)d_in[6];
    const int*  pos = (const int*)d_in[7];

    float* out = (float*)d_out;
    float* nk  = out + OUT_ELEMS;
    float* nv  = nk + KV_ELEMS;

    cudaFuncSetAttribute(gemm_h<0>, cudaFuncAttributeMaxDynamicSharedMemorySize, GEMM_SMEM);
    cudaFuncSetAttribute(gemm_h<1>, cudaFuncAttributeMaxDynamicSharedMemorySize, GEMM_SMEM);
    cudaFuncSetAttribute(attn_kernel, cudaFuncAttributeMaxDynamicSharedMemorySize, ATTN_SMEM);

    prep_kernel<<<dim3(1024,4),256>>>((const float4*)x,(const float4*)Wq,(const float4*)Wk,
                                      (const float4*)Wv,pos);
    gemm_h<0><<<dim3(16,32,4),128,GEMM_SMEM>>>((const float4*)pk,(const float4*)pv,nk,nv,nullptr);
    attn_kernel<<<1088,256,ATTN_SMEM>>>((const float4*)Wo);
    gemm_h<1><<<dim3(16,32,1),128,GEMM_SMEM>>>(nullptr,nullptr,nullptr,nullptr,out);
}